// round 1
// baseline (speedup 1.0000x reference)
#include <cuda_runtime.h>
#include <cstdint>

// Problem constants
#define NB     512          // batch n
#define LFULL  257          // L
#define HD     256          // h (feature dim)
#define LOUT   256          // l = L-1
#define KDIM   512          // 2*h
#define HID    256          // hidden
#define NLAB   50
#define NLABP  64           // padded

#define BM       64         // tokens per CTA
#define BK       32         // k-chunk
#define NCHUNK   (KDIM / BK)   // 16
#define THREADS  256
#define NTOK     (NB * LOUT)   // 131072
#define NBLK     (NTOK / BM)   // 2048

// __device__ scratch (allocation-free rule)
__device__ float g_W1T[KDIM * HID];      // [k][o]  (512 x 256)
__device__ float g_W2T[HID * NLABP];     // [k][j]  (256 x 64, j>=50 zero)
__device__ int   g_heads64;

// SMEM layout (bytes):
//   region1 [0, 131072):
//     phase1: A2 dup-pairs (u64[64*32] = 16KB) @0 ; B (f32[32*256] = 32KB) @16384
//     phase2: hid dup-pairs (u64[64*256] = 128KB) @0
//   w2t   @131072  (f32[256*64] = 64KB)
//   b1    @196608  (f32[256])
//   b2    @197632  (f32[64])
//   rows  @197888  (int[128])
#define SMEM_BYTES 198400

__global__ void prep_kernel(const float* __restrict__ W1,
                            const float* __restrict__ W2,
                            const void*  __restrict__ heads)
{
    int idx = blockIdx.x * blockDim.x + threadIdx.x;
    if (idx < KDIM * HID) {
        int h = idx >> 8;          // / HID
        int o = idx & (HID - 1);
        g_W1T[idx] = W1[o * KDIM + h];
    } else if (idx < KDIM * HID + HID * NLABP) {
        int i2 = idx - KDIM * HID;
        int k = i2 >> 6;
        int j = i2 & (NLABP - 1);
        g_W2T[i2] = (j < NLAB) ? W2[j * HID + k] : 0.0f;
    }
    if (idx == 0) {
        // Detect heads dtype: int64 => every odd 32-bit word is 0 (values < 257).
        const unsigned* h32 = (const unsigned*)heads;
        int is64 = 1;
        for (int i = 1; i < 128; i += 2) is64 &= (h32[i] == 0u);
        g_heads64 = is64;
    }
}

__device__ __forceinline__ unsigned long long dup_f32(float v) {
    unsigned long long d;
    asm("mov.b64 %0, {%1, %1};" : "=l"(d) : "r"(__float_as_uint(v)));
    return d;
}
__device__ __forceinline__ void unpack2(unsigned long long x, float& a, float& b) {
    unsigned lo, hi;
    asm("mov.b64 {%0, %1}, %2;" : "=r"(lo), "=r"(hi) : "l"(x));
    a = __uint_as_float(lo);
    b = __uint_as_float(hi);
}
__device__ __forceinline__ void fma2(unsigned long long& acc,
                                     unsigned long long a,
                                     unsigned long long b) {
    asm("fma.rn.f32x2 %0, %1, %2, %0;" : "+l"(acc) : "l"(a), "l"(b));
}

__global__ __launch_bounds__(THREADS, 1)
void label_kernel(const float* __restrict__ feat,
                  const void*  __restrict__ heads,
                  const float* __restrict__ b1,
                  const float* __restrict__ b2,
                  float*       __restrict__ out)
{
    extern __shared__ unsigned char smem_raw[];
    unsigned long long* A2_s   = (unsigned long long*)(smem_raw);           // phase1
    float*              B_s    = (float*)(smem_raw + 16384);                // phase1
    unsigned long long* hid2_s = (unsigned long long*)(smem_raw);           // phase2
    float*              w2t_s  = (float*)(smem_raw + 131072);
    float*              b1_s   = (float*)(smem_raw + 196608);
    float*              b2_s   = (float*)(smem_raw + 197632);
    int*                rows_s = (int*)(smem_raw + 197888);

    const int tid  = threadIdx.x;
    const int lane = tid & 31;
    const int wy   = tid >> 5;            // 0..7
    const int t0   = blockIdx.x * BM;

    // ---------------- preload ----------------
    {
        float4* wdst = (float4*)w2t_s;
        const float4* wsrc = (const float4*)g_W2T;
        #pragma unroll
        for (int i = 0; i < (HID * NLABP / 4) / THREADS; ++i)   // 16 iters
            wdst[tid + THREADS * i] = wsrc[tid + THREADS * i];
    }
    if (tid < HID)   b1_s[tid] = b1[tid];
    if (tid < NLABP) b2_s[tid] = (tid < NLAB) ? b2[tid] : 0.0f;
    if (tid < BM) {
        int t = t0 + tid;
        int n = t >> 8;
        int l = t & 255;
        rows_s[tid * 2] = n * LFULL + l + 1;
        int hv;
        if (g_heads64) hv = (int)((const long long*)heads)[t];
        else           hv = ((const int*)heads)[t];
        rows_s[tid * 2 + 1] = n * LFULL + hv;
    }
    __syncthreads();

    // ---------------- GEMM1: hid = relu(cat @ W1^T + b1) ----------------
    unsigned long long acc[8][4];
    #pragma unroll
    for (int r = 0; r < 8; ++r)
        #pragma unroll
        for (int c = 0; c < 4; ++c) acc[r][c] = 0ull;

    for (int kb = 0; kb < NCHUNK; ++kb) {
        const int side = kb >> 3;                  // 0: dependent, 1: head
        const int col0 = (kb * BK) & (HD - 1);

        // load A tile (dup pairs)
        #pragma unroll
        for (int i = 0; i < 8; ++i) {
            int m = wy * 8 + i;
            int row = rows_s[m * 2 + side];
            float v = feat[(size_t)row * HD + col0 + lane];
            A2_s[m * BK + lane] = dup_f32(v);
        }
        // load B tile (coalesced from transposed W1)
        {
            const float4* Bg4 = (const float4*)(g_W1T + kb * BK * HID);
            float4* Bs4 = (float4*)B_s;
            #pragma unroll
            for (int i = 0; i < 8; ++i)
                Bs4[tid + THREADS * i] = Bg4[tid + THREADS * i];
        }
        __syncthreads();

        const unsigned long long* Bu = (const unsigned long long*)B_s;
        #pragma unroll
        for (int k = 0; k < BK; ++k) {
            unsigned long long bv[4];
            const unsigned long long* Brow = Bu + k * (HID / 2);
            #pragma unroll
            for (int c = 0; c < 4; ++c) bv[c] = Brow[c * 32 + lane];
            #pragma unroll
            for (int r = 0; r < 8; ++r) {
                unsigned long long a2 = A2_s[(wy * 8 + r) * BK + k];
                #pragma unroll
                for (int c = 0; c < 4; ++c) fma2(acc[r][c], a2, bv[c]);
            }
        }
        __syncthreads();
    }

    // epilogue: bias + relu, store dup-pairs (overwrites A/B region)
    #pragma unroll
    for (int r = 0; r < 8; ++r) {
        int m = wy * 8 + r;
        #pragma unroll
        for (int c = 0; c < 4; ++c) {
            int o = c * 64 + lane * 2;
            float v0, v1;
            unpack2(acc[r][c], v0, v1);
            v0 = fmaxf(v0 + b1_s[o], 0.0f);
            v1 = fmaxf(v1 + b1_s[o + 1], 0.0f);
            hid2_s[m * HID + o]     = dup_f32(v0);
            hid2_s[m * HID + o + 1] = dup_f32(v1);
        }
    }
    __syncthreads();

    // ---------------- GEMM2: out = hid @ W2^T + b2 ----------------
    unsigned long long acc2[8];
    #pragma unroll
    for (int r = 0; r < 8; ++r) acc2[r] = 0ull;

    const unsigned long long* W2u = (const unsigned long long*)w2t_s; // [k][32]
    #pragma unroll 4
    for (int k = 0; k < HID; k += 2) {
        unsigned long long w0 = W2u[k * 32 + lane];
        unsigned long long w1 = W2u[k * 32 + 32 + lane];
        #pragma unroll
        for (int r = 0; r < 8; ++r) {
            const ulonglong2 h =
                *reinterpret_cast<const ulonglong2*>(&hid2_s[(wy * 8 + r) * HID + k]);
            fma2(acc2[r], h.x, w0);
            fma2(acc2[r], h.y, w1);
        }
    }

    const int j = lane * 2;
    if (j < NLAB) {
        float bb0 = b2_s[j], bb1 = b2_s[j + 1];
        #pragma unroll
        for (int r = 0; r < 8; ++r) {
            int m = wy * 8 + r;
            float v0, v1;
            unpack2(acc2[r], v0, v1);
            float2 res = make_float2(v0 + bb0, v1 + bb1);
            *reinterpret_cast<float2*>(out + (size_t)(t0 + m) * NLAB + j) = res;
        }
    }
}

extern "C" void kernel_launch(void* const* d_in, const int* in_sizes, int n_in,
                              void* d_out, int out_size)
{
    const float* feat  = (const float*)d_in[0];
    const void*  heads = d_in[1];
    // d_in[2] = masks (all ones, not used by reference output)
    const float* W1    = (const float*)d_in[3];
    const float* b1    = (const float*)d_in[4];
    const float* W2    = (const float*)d_in[5];
    const float* b2    = (const float*)d_in[6];
    float* out = (float*)d_out;

    prep_kernel<<<(KDIM * HID + HID * NLABP + 255) / 256, 256>>>(W1, W2, heads);

    cudaFuncSetAttribute(label_kernel,
                         cudaFuncAttributeMaxDynamicSharedMemorySize, SMEM_BYTES);
    label_kernel<<<NBLK, THREADS, SMEM_BYTES>>>(feat, heads, b1, b2, out);
}